// round 12
// baseline (speedup 1.0000x reference)
#include <cuda_runtime.h>
#include <cuda_fp16.h>
#include <cstdint>

#define NN 100000
#define NE 250000
#define D  300
#define LDH 320
#define LDHID 640
#define NL 5
#define INV2048 4.8828125e-4f

// ---------------- device-global scratch ------------------------------------
__device__ float  g_h  [(size_t)NN * LDH];
__device__ __half g_agg_hi[(size_t)NN * LDH];
__device__ int8_t g_qa1h[(size_t)NN * LDH];
__device__ int8_t g_qa1l[(size_t)NN * LDH];
__device__ float  g_sa1[NN];
__device__ __half g_hid_hi[(size_t)NN * LDHID];
__device__ __half g_hid_lo[(size_t)NN * LDHID];
__device__ int8_t g_qa2h[(size_t)NN * LDHID];
__device__ int8_t g_qa2l[(size_t)NN * LDHID];
__device__ float  g_sa2[NN];
__device__ float  g_h2 [(size_t)NN * LDH];
__device__ __half g_w1h[NL * 640 * LDH];
__device__ int8_t g_qw1h[NL * 640 * LDH];
__device__ int8_t g_qw1l[NL * 640 * LDH];
__device__ float  g_sw1[NL * 640];
__device__ __half g_w2h[NL * 384 * LDHID];
__device__ int8_t g_qw2h[NL * 384 * LDHID];
__device__ int8_t g_qw2l[NL * 384 * LDHID];
__device__ float  g_sw2[NL * 384];
__device__ float  g_b1p[NL * 640];
__device__ float  g_b2p[NL * LDH];
__device__ int    g_rowptr[NN + 1];
__device__ int    g_cnt[NN];
__device__ int    g_src[NE];
__device__ unsigned char g_ec[NE];
__device__ float  g_colsum[LDH], g_colsq[LDH], g_scale[LDH], g_shift[LDH];

// ---------------- PTX helpers ----------------------------------------------
__device__ __forceinline__ uint32_t smem_u32(const void* p) {
    uint32_t a;
    asm("{ .reg .u64 t; cvta.to.shared.u64 t, %1; cvt.u32.u64 %0, t; }"
        : "=r"(a) : "l"(p));
    return a;
}
__device__ __forceinline__ void cp16(uint32_t dst, const void* src, int srcbytes) {
    asm volatile("cp.async.cg.shared.global [%0], [%1], 16, %2;"
                 :: "r"(dst), "l"(src), "r"(srcbytes) : "memory");
}
#define CP_COMMIT() asm volatile("cp.async.commit_group;" ::: "memory")
#define CP_WAIT1()  asm volatile("cp.async.wait_group 1;" ::: "memory")
#define CP_WAIT0()  asm volatile("cp.async.wait_group 0;" ::: "memory")

__device__ __forceinline__ void mma_h(float* c, const uint32_t* a,
                                      uint32_t b0, uint32_t b1) {
    asm volatile(
        "mma.sync.aligned.m16n8k16.row.col.f32.f16.f16.f32 "
        "{%0,%1,%2,%3}, {%4,%5,%6,%7}, {%8,%9}, {%0,%1,%2,%3};"
        : "+f"(c[0]), "+f"(c[1]), "+f"(c[2]), "+f"(c[3])
        : "r"(a[0]), "r"(a[1]), "r"(a[2]), "r"(a[3]), "r"(b0), "r"(b1));
}
__device__ __forceinline__ void mma_i8(int* c, const uint32_t* a,
                                       uint32_t b0, uint32_t b1) {
    asm volatile(
        "mma.sync.aligned.m16n8k32.row.col.s32.s8.s8.s32 "
        "{%0,%1,%2,%3}, {%4,%5,%6,%7}, {%8,%9}, {%0,%1,%2,%3};"
        : "+r"(c[0]), "+r"(c[1]), "+r"(c[2]), "+r"(c[3])
        : "r"(a[0]), "r"(a[1]), "r"(a[2]), "r"(a[3]), "r"(b0), "r"(b1));
}
__device__ __forceinline__ void ldsm4(uint32_t& r0, uint32_t& r1,
                                      uint32_t& r2, uint32_t& r3, uint32_t addr) {
    asm volatile("ldmatrix.sync.aligned.m8n8.x4.shared.b16 {%0,%1,%2,%3}, [%4];"
                 : "=r"(r0), "=r"(r1), "=r"(r2), "=r"(r3) : "r"(addr));
}
__device__ __forceinline__ int8_t q8(float x) {
    int q = (int)rintf(x);
    q = q > 127 ? 127 : (q < -127 ? -127 : q);
    return (int8_t)q;
}

// ---------------- hybrid fp16+int8 GEMM: C = A(MxK)*B(NxK)^T + bias --------
// main term ah*bh in fp16 f32acc; cross terms (ah*bl + al*bh) in int8 with
// forced scales s_lo = s_hi*2^-11 -> single s32 accumulator.
// CTA tile 128(M) x 64(N), 8 warps (4M x 2N), warp tile 32x32.
// K chunk = 32 elements. fp16 odd-k16-tail skipped warp-uniformly; IMMA
// always full chunk (zero-padded operands).
#define SA_ST 80                 // fp16 tile row stride bytes (64B data + pad)
#define S8_ST 48                 // int8 tile row stride bytes (32B data + pad)
#define OFF_AH  0                // 128 x 80B   = 10240
#define OFF_QAH 10240            // 128 x 48B   =  6144
#define OFF_QAL 16384
#define OFF_BH  22528            // 64 x 80B    =  5120
#define OFF_QBH 27648            // 64 x 48B    =  3072
#define OFF_QBL 30720
#define STAGE_B 33792
#define GEMM_SMEM (2 * STAGE_B)  // 67584

__global__ __launch_bounds__(256, 2)
void hgemm_kernel(const __half* __restrict__ Ah, const int8_t* __restrict__ QAh,
                  const int8_t* __restrict__ QAl, const float* __restrict__ sA, int lda,
                  const __half* __restrict__ Bh, const int8_t* __restrict__ QBh,
                  const int8_t* __restrict__ QBl, const float* __restrict__ sB, int ldb,
                  float* __restrict__ Cf, __half* __restrict__ Chi, __half* __restrict__ Clo,
                  int ldc, const float* __restrict__ bias,
                  int M, int Npad, int nks, int outmode, int stats) {
    extern __shared__ char smc[];
    uint32_t sbase = smem_u32(smc);
    int tid = threadIdx.x;
    int wid = tid >> 5, lane = tid & 31;
    int warp_m = wid & 3, warp_n = wid >> 2;     // 4 x 2
    int g = lane >> 2, t = lane & 3;

    int m0 = blockIdx.y * 128;
    int n0 = blockIdx.x * 64;
    bool active = (warp_n * 32) < (Npad - n0);
    int nch = (nks + 1) >> 1;

    float accf[2][4][4];
    int   acci[2][4][4];
#pragma unroll
    for (int i = 0; i < 2; i++)
#pragma unroll
        for (int j = 0; j < 4; j++)
#pragma unroll
            for (int r = 0; r < 4; r++) { accf[i][j][r] = 0.f; acci[i][j][r] = 0; }

    // fragment lane bases (byte offsets within tiles)
    uint32_t a16b = (uint32_t)((warp_m * 32 + (lane & 15)) * SA_ST + (lane >> 4) * 16);
    uint32_t a8b  = (uint32_t)((warp_m * 32 + (lane & 15)) * S8_ST + (lane >> 4) * 16);
    uint32_t b16b = (uint32_t)((warp_n * 32 + (lane & 7) + ((lane >> 4) * 8)) * SA_ST
                               + ((lane >> 3) & 1) * 16);
    uint32_t b8b  = (uint32_t)((warp_n * 32 + (lane & 7) + ((lane >> 4) * 8)) * S8_ST
                               + ((lane >> 3) & 1) * 16);

#define LOAD_CHUNK(slot, kc) do {                                             \
    uint32_t st = sbase + (slot) * STAGE_B;                                   \
    _Pragma("unroll")                                                         \
    for (int it = 0; it < 2; it++) {                                          \
        int u = it * 256 + tid;                                               \
        int row = u >> 2, seg = u & 3;                                        \
        int gr = m0 + row;                                                    \
        bool va = gr < M;                                                     \
        cp16(st + OFF_AH + row * SA_ST + seg * 16,                            \
             Ah + (size_t)(va ? gr : 0) * lda + (kc) * 32 + seg * 8,          \
             va ? 16 : 0);                                                    \
    }                                                                         \
    {                                                                         \
        int row = tid >> 1, seg = tid & 1;                                    \
        int gr = m0 + row;                                                    \
        bool va = gr < M;                                                     \
        size_t go = (size_t)(va ? gr : 0) * lda + (kc) * 32 + seg * 16;       \
        cp16(st + OFF_QAH + row * S8_ST + seg * 16, QAh + go, va ? 16 : 0);   \
        cp16(st + OFF_QAL + row * S8_ST + seg * 16, QAl + go, va ? 16 : 0);   \
    }                                                                         \
    {                                                                         \
        int row = tid >> 2, seg = tid & 3;                                    \
        cp16(st + OFF_BH + row * SA_ST + seg * 16,                            \
             Bh + (size_t)(n0 + row) * ldb + (kc) * 32 + seg * 8, 16);        \
    }                                                                         \
    if (tid < 128) {                                                          \
        int row = tid >> 1, seg = tid & 1;                                    \
        cp16(st + OFF_QBH + row * S8_ST + seg * 16,                           \
             QBh + (size_t)(n0 + row) * ldb + (kc) * 32 + seg * 16, 16);      \
    } else {                                                                  \
        int t2 = tid - 128;                                                   \
        int row = t2 >> 1, seg = t2 & 1;                                      \
        cp16(st + OFF_QBL + row * S8_ST + seg * 16,                           \
             QBl + (size_t)(n0 + row) * ldb + (kc) * 32 + seg * 16, 16);      \
    }                                                                         \
} while (0)

// fp16 main-term body for one k16 step
#define DO_KS(ks) do {                                                        \
    uint32_t ah[2][4], bhf[4][2];                                             \
    _Pragma("unroll")                                                         \
    for (int i = 0; i < 2; i++)                                               \
        ldsm4(ah[i][0], ah[i][1], ah[i][2], ah[i][3],                         \
              tAH + a16b + i * 16 * SA_ST + (ks) * 32);                       \
    _Pragma("unroll")                                                         \
    for (int jj = 0; jj < 2; jj++)                                            \
        ldsm4(bhf[2*jj][0], bhf[2*jj][1], bhf[2*jj+1][0], bhf[2*jj+1][1],     \
              tBH + b16b + jj * 16 * SA_ST + (ks) * 32);                      \
    _Pragma("unroll")                                                         \
    for (int j = 0; j < 4; j++)                                               \
        _Pragma("unroll")                                                     \
        for (int i = 0; i < 2; i++)                                           \
            mma_h(accf[i][j], ah[i], bhf[j][0], bhf[j][1]);                   \
} while (0)

    LOAD_CHUNK(0, 0);
    CP_COMMIT();
    LOAD_CHUNK(1, 1);
    CP_COMMIT();
    CP_WAIT1();
    __syncthreads();

    for (int k = 0; k < nch; k++) {
        int slot = k & 1;
        uint32_t st = sbase + slot * STAGE_B;
        uint32_t tAH = st + OFF_AH,  tQAH = st + OFF_QAH, tQAL = st + OFF_QAL;
        uint32_t tBH = st + OFF_BH,  tQBH = st + OFF_QBH, tQBL = st + OFF_QBL;
        if (active) {
            // int8 cross terms (full k32)
            uint32_t qa[2][4], ql[2][4], qbh[4][2], qbl[4][2];
#pragma unroll
            for (int i = 0; i < 2; i++) {
                ldsm4(qa[i][0], qa[i][1], qa[i][2], qa[i][3],
                      tQAH + a8b + i * 16 * S8_ST);
                ldsm4(ql[i][0], ql[i][1], ql[i][2], ql[i][3],
                      tQAL + a8b + i * 16 * S8_ST);
            }
#pragma unroll
            for (int jj = 0; jj < 2; jj++) {
                ldsm4(qbh[2*jj][0], qbh[2*jj][1], qbh[2*jj+1][0], qbh[2*jj+1][1],
                      tQBH + b8b + jj * 16 * S8_ST);
                ldsm4(qbl[2*jj][0], qbl[2*jj][1], qbl[2*jj+1][0], qbl[2*jj+1][1],
                      tQBL + b8b + jj * 16 * S8_ST);
            }
#pragma unroll
            for (int j = 0; j < 4; j++)
#pragma unroll
                for (int i = 0; i < 2; i++) {
                    mma_i8(acci[i][j], qa[i], qbl[j][0], qbl[j][1]);
                    mma_i8(acci[i][j], ql[i], qbh[j][0], qbh[j][1]);
                }
            // fp16 main term
            DO_KS(0);
            if (2 * k + 2 <= nks) {
                DO_KS(1);
            }
        }
        __syncthreads();
        if (k + 2 < nch) {
            LOAD_CHUNK(slot, k + 2);
            CP_COMMIT();
            CP_WAIT1();
        } else {
            CP_WAIT0();
        }
        __syncthreads();
    }
#undef DO_KS
#undef LOAD_CHUNK

    // epilogue: out = accf + sA*sB*2^-11*acci + bias
    if (active) {
        float cs[4][2], cq[4][2];
#pragma unroll
        for (int j = 0; j < 4; j++) {
            cs[j][0] = cs[j][1] = 0.f;
            cq[j][0] = cq[j][1] = 0.f;
        }
#pragma unroll
        for (int i = 0; i < 2; i++) {
            int r0 = m0 + warp_m * 32 + i * 16 + g;
            float saf[2];
            saf[0] = (r0 < M) ? __ldg(sA + r0) * INV2048 : 0.f;
            saf[1] = (r0 + 8 < M) ? __ldg(sA + r0 + 8) * INV2048 : 0.f;
#pragma unroll
            for (int j = 0; j < 4; j++) {
                int col = n0 + warp_n * 32 + j * 8 + 2 * t;
                if (col >= Npad) continue;
                float2 bv = *(const float2*)(bias + col);
                float2 sb = *(const float2*)(sB + col);
#pragma unroll
                for (int h = 0; h < 2; h++) {
                    int r = r0 + 8 * h;
                    if (r >= M) continue;
                    float vx = accf[i][j][2*h]   + saf[h] * sb.x * (float)acci[i][j][2*h]   + bv.x;
                    float vy = accf[i][j][2*h+1] + saf[h] * sb.y * (float)acci[i][j][2*h+1] + bv.y;
                    if (outmode == 1) {
                        vx = fmaxf(vx, 0.f); vy = fmaxf(vy, 0.f);
                        __half hx = __float2half(vx);
                        __half hy = __float2half(vy);
                        __half lx = __float2half(vx - __half2float(hx));
                        __half ly = __float2half(vy - __half2float(hy));
                        *(half2*)(Chi + (size_t)r * ldc + col) = __halves2half2(hx, hy);
                        *(half2*)(Clo + (size_t)r * ldc + col) = __halves2half2(lx, ly);
                    } else {
                        float2 v; v.x = vx; v.y = vy;
                        *(float2*)(Cf + (size_t)r * ldc + col) = v;
                        if (stats) {
                            cs[j][0] += vx; cq[j][0] += vx * vx;
                            cs[j][1] += vy; cq[j][1] += vy * vy;
                        }
                    }
                }
            }
        }
        if (stats) {
#pragma unroll
            for (int j = 0; j < 4; j++)
#pragma unroll
                for (int h = 0; h < 2; h++) {
#pragma unroll
                    for (int off = 16; off >= 4; off >>= 1) {
                        cs[j][h] += __shfl_down_sync(0xffffffff, cs[j][h], off);
                        cq[j][h] += __shfl_down_sync(0xffffffff, cq[j][h], off);
                    }
                }
            if (lane < 4) {
#pragma unroll
                for (int j = 0; j < 4; j++)
#pragma unroll
                    for (int h = 0; h < 2; h++) {
                        int col = n0 + warp_n * 32 + j * 8 + 2 * lane + h;
                        if (col < D) {
                            atomicAdd(&g_colsum[col], cs[j][h]);
                            atomicAdd(&g_colsq[col], cq[j][h]);
                        }
                    }
            }
        }
    }
}

// ---------------- input embedding -------------------------------------------
__global__ __launch_bounds__(LDH)
void init_h_kernel(const int* __restrict__ x,
                   const float* __restrict__ t1,
                   const float* __restrict__ t2) {
    int f = threadIdx.x;
    size_t i = blockIdx.x;
    float v = 0.f;
    if (f < D) {
        int a = x[2 * i];
        int b = x[2 * i + 1];
        v = t1[a * D + f] + t2[b * D + f];
    }
    g_h[i * LDH + f] = v;
}

// ---------------- weight packing: fp16 hi + int8 quant (row scales) ---------
__global__ __launch_bounds__(LDH)
void pack_w1_kernel(const float* __restrict__ w1) {
    __shared__ float red[LDH];
    int k = threadIdx.x;
    int r = blockIdx.x;
    int l = r / 640, row = r % 640;
    float v = 0.f;
    if (row < 600 && k < D) v = w1[(size_t)(l * 600 + row) * D + k];
    red[k] = fabsf(v);
    __syncthreads();
    for (int s = 256; s > 0; s >>= 1) {
        if (k < s && k + s < LDH) red[k] = fmaxf(red[k], red[k + s]);
        __syncthreads();
    }
    float m = red[0];
    float sa = m > 0.f ? m * (1.f / 127.f) : 1.f;
    __half hi = __float2half(v);
    float fh = __half2float(hi);
    float lo = v - fh;
    size_t o = (size_t)r * LDH + k;
    g_w1h[o]  = hi;
    g_qw1h[o] = q8(fh / sa);
    g_qw1l[o] = q8(lo * 2048.f / sa);
    if (k == 0) g_sw1[r] = sa;
}
__global__ __launch_bounds__(LDHID)
void pack_w2_kernel(const float* __restrict__ w2) {
    __shared__ float red[LDHID];
    int k = threadIdx.x;
    int r = blockIdx.x;
    int l = r / 384, row = r % 384;
    float v = 0.f;
    if (row < D && k < 600) v = w2[(size_t)(l * D + row) * 600 + k];
    red[k] = fabsf(v);
    __syncthreads();
    for (int s = 512; s > 0; s >>= 1) {
        if (k < s && k + s < LDHID) red[k] = fmaxf(red[k], red[k + s]);
        __syncthreads();
    }
    float m = red[0];
    float sa = m > 0.f ? m * (1.f / 127.f) : 1.f;
    __half hi = __float2half(v);
    float fh = __half2float(hi);
    float lo = v - fh;
    size_t o = (size_t)r * LDHID + k;
    g_w2h[o]  = hi;
    g_qw2h[o] = q8(fh / sa);
    g_qw2l[o] = q8(lo * 2048.f / sa);
    if (k == 0) g_sw2[r] = sa;
}
__global__ __launch_bounds__(256)
void pack_b1_kernel(const float* __restrict__ b1) {
    int i = blockIdx.x * 256 + threadIdx.x;
    if (i >= NL * 640) return;
    int l = i / 640, c = i % 640;
    g_b1p[i] = (c < 600) ? b1[l * 600 + c] : 0.f;
}
__global__ __launch_bounds__(256)
void pack_b2_kernel(const float* __restrict__ b2) {
    int i = blockIdx.x * 256 + threadIdx.x;
    if (i >= NL * LDH) return;
    int l = i / LDH, c = i % LDH;
    g_b2p[i] = (c < D) ? b2[l * D + c] : 0.f;
}

// ---------------- hid quantization (per-row scale) ---------------------------
__global__ __launch_bounds__(256)
void quant_hid_kernel() {
    __shared__ float red[256];
    int tid = threadIdx.x;
    size_t row = blockIdx.x;
    const __half* ph = g_hid_hi + row * LDHID;
    const __half* pl = g_hid_lo + row * LDHID;
    float m = 0.f;
    for (int f = tid; f < 608; f += 256)
        m = fmaxf(m, fabsf(__half2float(ph[f])));
    red[tid] = m;
    __syncthreads();
    for (int s = 128; s > 0; s >>= 1) {
        if (tid < s) red[tid] = fmaxf(red[tid], red[tid + s]);
        __syncthreads();
    }
    float mx = red[0];
    float sa = mx > 0.f ? mx * (1.f / 127.f) : 1.f;
    float inv = 1.f / sa;
    for (int f = tid; f < 608; f += 256) {
        g_qa2h[row * LDHID + f] = q8(__half2float(ph[f]) * inv);
        g_qa2l[row * LDHID + f] = q8(__half2float(pl[f]) * 2048.f * inv);
    }
    if (tid == 0) g_sa2[row] = sa;
}

// ---------------- CSR build (dst-sorted) ------------------------------------
__global__ __launch_bounds__(256)
void zero_cnt_kernel() {
    int i = blockIdx.x * blockDim.x + threadIdx.x;
    if (i < NN) g_cnt[i] = 0;
}
__global__ __launch_bounds__(256)
void hist_kernel(const int* __restrict__ ei) {
    int e = blockIdx.x * blockDim.x + threadIdx.x;
    if (e < NE) atomicAdd(&g_cnt[ei[NE + e]], 1);
}
__global__ __launch_bounds__(512)
void scan_kernel() {
    __shared__ int s[512];
    const int CH = (NN + 511) / 512;
    int t = threadIdx.x;
    int base = t * CH;
    int sum = 0;
#pragma unroll 1
    for (int i = 0; i < CH; i++) {
        int idx = base + i;
        if (idx < NN) sum += g_cnt[idx];
    }
    s[t] = sum;
    __syncthreads();
    for (int off = 1; off < 512; off <<= 1) {
        int v = (t >= off) ? s[t - off] : 0;
        __syncthreads();
        s[t] += v;
        __syncthreads();
    }
    int run = s[t] - sum;
#pragma unroll 1
    for (int i = 0; i < CH; i++) {
        int idx = base + i;
        if (idx < NN) { g_rowptr[idx] = run; run += g_cnt[idx]; }
    }
    if (t == 511) g_rowptr[NN] = s[511];
}
__global__ __launch_bounds__(256)
void scatter_kernel(const int* __restrict__ ei,
                    const int* __restrict__ ea) {
    int e = blockIdx.x * blockDim.x + threadIdx.x;
    if (e >= NE) return;
    int srcv = ei[e];
    int dstv = ei[NE + e];
    int pos = g_rowptr[dstv] + atomicAdd(&g_cnt[dstv], 1);
    g_src[pos] = srcv;
    g_ec[pos] = (unsigned char)(ea[2 * e] * 3 + ea[2 * e + 1]);
}

// ---------------- gather-aggregate + fused BN/ReLU + quantization ------------
__global__ __launch_bounds__(256)
void agg_kernel(const float* __restrict__ X,
                const float* __restrict__ e1,
                const float* __restrict__ e2,
                int transform) {
    __shared__ float etab[18 * D];
    int tid = threadIdx.x;
    for (int idx = tid; idx < 18 * D; idx += 256) {
        int c = idx / D, f = idx - c * D;
        etab[idx] = e1[(c / 3) * D + f] + e2[(c % 3) * D + f];
    }
    __syncthreads();
    int warp = tid >> 5, lane = tid & 31;
    int node = blockIdx.x * 8 + warp;
    if (node >= NN) return;

    float sc[10], sh[10];
#pragma unroll
    for (int j = 0; j < 10; j++) {
        int f = lane + 32 * j;
        if (transform && f < D) { sc[j] = g_scale[f]; sh[j] = g_shift[f]; }
        else { sc[j] = 1.f; sh[j] = 0.f; }
    }

    float acc[10];
    const float* hr = X + (size_t)node * LDH;
#pragma unroll
    for (int j = 0; j < 10; j++) {
        int f = lane + 32 * j;
        if (f < D) {
            float v = fmaf(hr[f], sc[j], sh[j]);
            if (transform) v = fmaxf(v, 0.f);
            acc[j] = v + etab[12 * D + f];   // self loop code 12
        } else acc[j] = 0.f;
    }
    int beg = g_rowptr[node];
    int end = g_rowptr[node + 1];
#pragma unroll 1
    for (int e = beg; e < end; e++) {
        int s = g_src[e];
        const float* et = etab + (int)g_ec[e] * D;
        const float* hs = X + (size_t)s * LDH;
#pragma unroll
        for (int j = 0; j < 10; j++) {
            int f = lane + 32 * j;
            if (f < D) {
                float v = fmaf(hs[f], sc[j], sh[j]);
                if (transform) v = fmaxf(v, 0.f);
                acc[j] += v + et[f];
            }
        }
    }
    // row max for int8 scale
    float m = 0.f;
#pragma unroll
    for (int j = 0; j < 10; j++) m = fmaxf(m, fabsf(acc[j]));
#pragma unroll
    for (int off = 16; off > 0; off >>= 1)
        m = fmaxf(m, __shfl_xor_sync(0xffffffff, m, off));
    float sa = m > 0.f ? m * (1.f / 127.f) : 1.f;
    float inv = 1.f / sa;

    size_t base = (size_t)node * LDH;
#pragma unroll
    for (int j = 0; j < 10; j++) {
        int f = lane + 32 * j;
        float v = acc[j];
        __half hi = __float2half(v);
        float fh = __half2float(hi);
        float lo = v - fh;
        g_agg_hi[base + f] = hi;
        g_qa1h[base + f] = q8(fh * inv);
        g_qa1l[base + f] = q8(lo * 2048.f * inv);
    }
    if (lane == 0) g_sa1[node] = sa;
}

// ---------------- BatchNorm helpers -----------------------------------------
__global__ __launch_bounds__(LDH)
void zero_stats_kernel() {
    int f = threadIdx.x;
    g_colsum[f] = 0.f; g_colsq[f] = 0.f;
}
__global__ __launch_bounds__(LDH)
void bn_final_kernel(const float* __restrict__ gamma,
                     const float* __restrict__ beta) {
    int f = threadIdx.x;
    if (f < D) {
        float inv_n = 1.f / (float)NN;
        float mean = g_colsum[f] * inv_n;
        float var  = g_colsq[f] * inv_n - mean * mean;
        float sc = gamma[f] * rsqrtf(var + 1e-5f);
        g_scale[f] = sc;
        g_shift[f] = beta[f] - mean * sc;
    }
    g_colsum[f] = 0.f;
    g_colsq[f] = 0.f;
}
__global__ __launch_bounds__(LDH)
void bn_apply_out_kernel(const float* __restrict__ X, float* __restrict__ out) {
    int f = threadIdx.x;
    if (f >= D) return;
    size_t i = blockIdx.x;
    out[i * (size_t)D + f] = X[i * LDH + f] * g_scale[f] + g_shift[f];
}

// ---------------- launch ----------------------------------------------------
extern "C" void kernel_launch(void* const* d_in, const int* in_sizes, int n_in,
                              void* d_out, int out_size) {
    const int*   x     = (const int*)d_in[0];
    const int*   ei    = (const int*)d_in[1];
    const int*   ea    = (const int*)d_in[2];
    const float* xe1   = (const float*)d_in[3];
    const float* xe2   = (const float*)d_in[4];
    const float* ee1   = (const float*)d_in[5];
    const float* ee2   = (const float*)d_in[6];
    const float* w1    = (const float*)d_in[7];
    const float* b1    = (const float*)d_in[8];
    const float* w2    = (const float*)d_in[9];
    const float* b2    = (const float*)d_in[10];
    const float* gamma = (const float*)d_in[11];
    const float* beta  = (const float*)d_in[12];
    float* out = (float*)d_out;

    float *h, *h2, *b1p, *b2p, *sa1, *sa2, *sw1, *sw2;
    __half *agg_hi, *hid_hi, *hid_lo, *w1h, *w2h;
    int8_t *qa1h, *qa1l, *qa2h, *qa2l, *qw1h, *qw1l, *qw2h, *qw2l;
    cudaGetSymbolAddress((void**)&h,      g_h);
    cudaGetSymbolAddress((void**)&h2,     g_h2);
    cudaGetSymbolAddress((void**)&agg_hi, g_agg_hi);
    cudaGetSymbolAddress((void**)&hid_hi, g_hid_hi);
    cudaGetSymbolAddress((void**)&hid_lo, g_hid_lo);
    cudaGetSymbolAddress((void**)&w1h,    g_w1h);
    cudaGetSymbolAddress((void**)&w2h,    g_w2h);
    cudaGetSymbolAddress((void**)&qa1h,   g_qa1h);
    cudaGetSymbolAddress((void**)&qa1l,   g_qa1l);
    cudaGetSymbolAddress((void**)&qa2h,   g_qa2h);
    cudaGetSymbolAddress((void**)&qa2l,   g_qa2l);
    cudaGetSymbolAddress((void**)&qw1h,   g_qw1h);
    cudaGetSymbolAddress((void**)&qw1l,   g_qw1l);
    cudaGetSymbolAddress((void**)&qw2h,   g_qw2h);
    cudaGetSymbolAddress((void**)&qw2l,   g_qw2l);
    cudaGetSymbolAddress((void**)&sa1,    g_sa1);
    cudaGetSymbolAddress((void**)&sa2,    g_sa2);
    cudaGetSymbolAddress((void**)&sw1,    g_sw1);
    cudaGetSymbolAddress((void**)&sw2,    g_sw2);
    cudaGetSymbolAddress((void**)&b1p,    g_b1p);
    cudaGetSymbolAddress((void**)&b2p,    g_b2p);

    static int smem_set = 0;
    if (!smem_set) {
        cudaFuncSetAttribute(hgemm_kernel,
                             cudaFuncAttributeMaxDynamicSharedMemorySize, GEMM_SMEM);
        smem_set = 1;
    }

    // prep
    pack_w1_kernel<<<NL * 640, LDH>>>(w1);
    pack_w2_kernel<<<NL * 384, LDHID>>>(w2);
    pack_b1_kernel<<<(NL * 640 + 255) / 256, 256>>>(b1);
    pack_b2_kernel<<<(NL * LDH + 255) / 256, 256>>>(b2);
    zero_stats_kernel<<<1, LDH>>>();
    init_h_kernel<<<NN, LDH>>>(x, xe1, xe2);

    // CSR build
    zero_cnt_kernel<<<(NN + 255) / 256, 256>>>();
    hist_kernel<<<(NE + 255) / 256, 256>>>(ei);
    scan_kernel<<<1, 512>>>();
    zero_cnt_kernel<<<(NN + 255) / 256, 256>>>();
    scatter_kernel<<<(NE + 255) / 256, 256>>>(ei, ea);

    const int MT = (NN + 127) / 128;   // 782
    for (int l = 0; l < NL; l++) {
        agg_kernel<<<(NN + 7) / 8, 256>>>(l == 0 ? h : h2,
                                          ee1 + l * 6 * D, ee2 + l * 3 * D,
                                          l > 0 ? 1 : 0);

        // GEMM1: M=NN, Npad=608 (10 N-tiles of 64), K 19 k16-steps (=304)
        hgemm_kernel<<<dim3(10, MT), 256, GEMM_SMEM>>>(
            agg_hi, qa1h, qa1l, sa1, LDH,
            w1h + (size_t)l * 640 * LDH, qw1h + (size_t)l * 640 * LDH,
            qw1l + (size_t)l * 640 * LDH, sw1 + l * 640, LDH,
            nullptr, hid_hi, hid_lo, LDHID, b1p + l * 640,
            NN, 608, 19, 1, 0);

        quant_hid_kernel<<<NN, 256>>>();

        // GEMM2: Npad=320 (5 N-tiles), K 38 k16-steps (=608), stats fused
        hgemm_kernel<<<dim3(5, MT), 256, GEMM_SMEM>>>(
            hid_hi, qa2h, qa2l, sa2, LDHID,
            w2h + (size_t)l * 384 * LDHID, qw2h + (size_t)l * 384 * LDHID,
            qw2l + (size_t)l * 384 * LDHID, sw2 + l * 384, LDHID,
            h2, nullptr, nullptr, LDH, b2p + l * LDH,
            NN, 320, 38, 0, 1);

        bn_final_kernel<<<1, LDH>>>(gamma + l * D, beta + l * D);

        if (l == NL - 1)
            bn_apply_out_kernel<<<NN, LDH>>>(h2, out);
    }
}

// round 13
// speedup vs baseline: 2.2468x; 2.2468x over previous
#include <cuda_runtime.h>
#include <cuda_fp16.h>
#include <cstdint>

#define NN 100000
#define NE 250000
#define D  300
#define LDH 320
#define LDHID 640
#define NL 5

// ---------------- device-global scratch ------------------------------------
__device__ float  g_h  [(size_t)NN * LDH];
__device__ __half g_agg_hi[(size_t)NN * LDH];
__device__ __half g_agg_lo[(size_t)NN * LDH];
__device__ __half g_hid_hi[(size_t)NN * LDHID];
__device__ __half g_hid_lo[(size_t)NN * LDHID];
__device__ float  g_h2 [(size_t)NN * LDH];
__device__ __half g_w1hi[NL * 640 * LDH];
__device__ __half g_w1lo[NL * 640 * LDH];
__device__ __half g_w2hi[NL * 384 * LDHID];
__device__ __half g_w2lo[NL * 384 * LDHID];
__device__ float  g_b1p[NL * 640];
__device__ float  g_b2p[NL * LDH];
__device__ int    g_rowptr[NN + 1];
__device__ int    g_cnt[NN];
__device__ int    g_src[NE];
__device__ unsigned char g_ec[NE];
__device__ float  g_colsum[LDH], g_colsq[LDH], g_scale[LDH], g_shift[LDH];

// ---------------- PTX helpers ----------------------------------------------
__device__ __forceinline__ uint32_t smem_u32(const void* p) {
    uint32_t a;
    asm("{ .reg .u64 t; cvta.to.shared.u64 t, %1; cvt.u32.u64 %0, t; }"
        : "=r"(a) : "l"(p));
    return a;
}
__device__ __forceinline__ void cp16(uint32_t dst, const void* src, int srcbytes) {
    asm volatile("cp.async.cg.shared.global [%0], [%1], 16, %2;"
                 :: "r"(dst), "l"(src), "r"(srcbytes) : "memory");
}
#define CP_COMMIT() asm volatile("cp.async.commit_group;" ::: "memory")
#define CP_WAIT1()  asm volatile("cp.async.wait_group 1;" ::: "memory")
#define CP_WAIT0()  asm volatile("cp.async.wait_group 0;" ::: "memory")

__device__ __forceinline__ void mma_h(float* c, const uint32_t* a,
                                      uint32_t b0, uint32_t b1) {
    asm volatile(
        "mma.sync.aligned.m16n8k16.row.col.f32.f16.f16.f32 "
        "{%0,%1,%2,%3}, {%4,%5,%6,%7}, {%8,%9}, {%0,%1,%2,%3};"
        : "+f"(c[0]), "+f"(c[1]), "+f"(c[2]), "+f"(c[3])
        : "r"(a[0]), "r"(a[1]), "r"(a[2]), "r"(a[3]), "r"(b0), "r"(b1));
}
__device__ __forceinline__ void ldsm4(uint32_t& r0, uint32_t& r1,
                                      uint32_t& r2, uint32_t& r3, uint32_t addr) {
    asm volatile("ldmatrix.sync.aligned.m8n8.x4.shared.b16 {%0,%1,%2,%3}, [%4];"
                 : "=r"(r0), "=r"(r1), "=r"(r2), "=r"(r3) : "r"(addr));
}

__device__ __forceinline__ void split_h(float v, __half& hi, __half& lo) {
    hi = __float2half(v);
    lo = __float2half(v - __half2float(hi));
}

// ---------------- 3-term fp16 split GEMM: C = A(MxK)*B(NxK)^T + bias --------
// All MMAs fp16 f32-accumulate: ah*bh + ah*bl + al*bh.
// CTA tile 128x128 (N tail warp-granular), K in k16 steps (odd tail skipped
// via one warp-uniform branch around a straight-line body), 2-stage cp.async,
// 8 warps (2Mx4N), warp tile 64x32, ldmatrix fragments, occupancy 2.
#define SSTR 20                          // smem row stride in u32 (32 fp16 + pad)
#define TILE_U32 (128 * SSTR)
#define STAGE_B (4 * TILE_U32 * 4)       // 40960 bytes
#define GEMM_SMEM (2 * STAGE_B)          // 81920

__global__ __launch_bounds__(256, 2)
void hgemm_kernel(const __half* __restrict__ Ahi, const __half* __restrict__ Alo, int lda,
                  const __half* __restrict__ Bhi, const __half* __restrict__ Blo, int ldb,
                  float* __restrict__ Cf, __half* __restrict__ Chi, __half* __restrict__ Clo,
                  int ldc, const float* __restrict__ bias,
                  int M, int Npad, int nks, int outmode, int stats) {
    extern __shared__ uint32_t smu[];
    uint32_t sbase = smem_u32(smu);
    int tid = threadIdx.x;
    int wid = tid >> 5, lane = tid & 31;
    int warp_m = wid & 1, warp_n = wid >> 1;     // 2 x 4
    int g = lane >> 2, t = lane & 3;

    int m0 = blockIdx.y * 128;
    int n0 = blockIdx.x * 128;
    bool active = (warp_n * 32) < (Npad - n0);   // warp-granular N tail
    int nch = (nks + 1) >> 1;                    // number of 32-wide chunks

    float acc[4][4][4];
#pragma unroll
    for (int i = 0; i < 4; i++)
#pragma unroll
        for (int j = 0; j < 4; j++)
#pragma unroll
            for (int r = 0; r < 4; r++) acc[i][j][r] = 0.f;

    int la_row = warp_m * 64 + (lane & 15);
    int la_ksel = (lane >> 4) * 4;
    int lb_row = warp_n * 32 + (lane & 7) + ((lane >> 4) * 8);
    int lb_ksel = ((lane >> 3) & 1) * 4;

    int rowL[2], qL[2];
#pragma unroll
    for (int it = 0; it < 2; it++) {
        int idx = it * 256 + tid;
        rowL[it] = idx >> 2;
        qL[it] = idx & 3;
    }

#define LOAD_CHUNK(slot, kc) do {                                             \
    uint32_t sAh = sbase + (slot) * STAGE_B;                                  \
    uint32_t sAl = sAh + TILE_U32 * 4;                                        \
    uint32_t sBh = sAl + TILE_U32 * 4;                                        \
    uint32_t sBl = sBh + TILE_U32 * 4;                                        \
    _Pragma("unroll")                                                         \
    for (int it = 0; it < 2; it++) {                                          \
        int row = rowL[it], q = qL[it];                                       \
        uint32_t so = (uint32_t)(row * SSTR * 4 + q * 16);                    \
        int gr = m0 + row;                                                    \
        bool va = gr < M;                                                     \
        size_t aoff = (size_t)(va ? gr : 0) * lda + (kc) * 32 + q * 8;        \
        cp16(sAh + so, Ahi + aoff, va ? 16 : 0);                              \
        cp16(sAl + so, Alo + aoff, va ? 16 : 0);                              \
        size_t boff = (size_t)(n0 + row) * ldb + (kc) * 32 + q * 8;           \
        cp16(sBh + so, Bhi + boff, 16);                                       \
        cp16(sBl + so, Blo + boff, 16);                                       \
    }                                                                         \
} while (0)

// straight-line body for one k16 step (no internal branches)
#define DO_KS(ks) do {                                                        \
    uint32_t aAoff = (uint32_t)((la_row * SSTR + (ks) * 8 + la_ksel) * 4);    \
    uint32_t aBoff = (uint32_t)((lb_row * SSTR + (ks) * 8 + lb_ksel) * 4);    \
    uint32_t ah[4][4], al[4][4];                                              \
    _Pragma("unroll")                                                         \
    for (int i = 0; i < 4; i++) {                                             \
        uint32_t off = aAoff + (uint32_t)(i * 16 * SSTR * 4);                 \
        ldsm4(ah[i][0], ah[i][1], ah[i][2], ah[i][3], tAh + off);             \
        ldsm4(al[i][0], al[i][1], al[i][2], al[i][3], tAl + off);             \
    }                                                                         \
    uint32_t bh[4][2], bl[4][2];                                              \
    _Pragma("unroll")                                                         \
    for (int jj = 0; jj < 2; jj++) {                                          \
        uint32_t off = aBoff + (uint32_t)(jj * 16 * SSTR * 4);                \
        ldsm4(bh[2 * jj][0], bh[2 * jj][1], bh[2 * jj + 1][0], bh[2 * jj + 1][1], tBh + off); \
        ldsm4(bl[2 * jj][0], bl[2 * jj][1], bl[2 * jj + 1][0], bl[2 * jj + 1][1], tBl + off); \
    }                                                                         \
    _Pragma("unroll")                                                         \
    for (int j = 0; j < 4; j++) {                                             \
        _Pragma("unroll")                                                     \
        for (int i = 0; i < 4; i++) {                                         \
            mma_h(acc[i][j], ah[i], bh[j][0], bh[j][1]);                      \
            mma_h(acc[i][j], ah[i], bl[j][0], bl[j][1]);                      \
            mma_h(acc[i][j], al[i], bh[j][0], bh[j][1]);                      \
        }                                                                     \
    }                                                                         \
} while (0)

    LOAD_CHUNK(0, 0);
    CP_COMMIT();
    if (nch > 1) LOAD_CHUNK(1, 1);
    CP_COMMIT();
    CP_WAIT1();
    __syncthreads();

    for (int k = 0; k < nch; k++) {
        int slot = k & 1;
        uint32_t tAh = sbase + slot * STAGE_B;
        uint32_t tAl = tAh + TILE_U32 * 4;
        uint32_t tBh = tAl + TILE_U32 * 4;
        uint32_t tBl = tBh + TILE_U32 * 4;
        if (active) {
            DO_KS(0);
            if (2 * k + 2 <= nks) {      // warp-uniform: skip only the odd tail
                DO_KS(1);
            }
        }
        __syncthreads();
        if (k + 2 < nch) {
            LOAD_CHUNK(slot, k + 2);
            CP_COMMIT();
            CP_WAIT1();
        } else {
            CP_WAIT0();
        }
        __syncthreads();
    }
#undef DO_KS
#undef LOAD_CHUNK

    // epilogue
    if (active) {
        float cs[4][2], cq[4][2];
#pragma unroll
        for (int j = 0; j < 4; j++) {
            cs[j][0] = cs[j][1] = 0.f;
            cq[j][0] = cq[j][1] = 0.f;
        }
#pragma unroll
        for (int i = 0; i < 4; i++) {
            int row = m0 + warp_m * 64 + i * 16 + g;
#pragma unroll
            for (int j = 0; j < 4; j++) {
                int col = n0 + warp_n * 32 + j * 8 + 2 * t;
                if (col >= Npad) continue;
                float2 bv = *(const float2*)(bias + col);
#pragma unroll
                for (int h = 0; h < 2; h++) {
                    int r = row + h * 8;
                    if (r >= M) continue;
                    float vx = acc[i][j][2 * h + 0] + bv.x;
                    float vy = acc[i][j][2 * h + 1] + bv.y;
                    if (outmode == 1) {
                        vx = fmaxf(vx, 0.f); vy = fmaxf(vy, 0.f);
                        __half hx, lx, hy, ly;
                        split_h(vx, hx, lx);
                        split_h(vy, hy, ly);
                        *(half2*)(Chi + (size_t)r * ldc + col) = __halves2half2(hx, hy);
                        *(half2*)(Clo + (size_t)r * ldc + col) = __halves2half2(lx, ly);
                    } else {
                        float2 v; v.x = vx; v.y = vy;
                        *(float2*)(Cf + (size_t)r * ldc + col) = v;
                        if (stats) {
                            cs[j][0] += vx; cq[j][0] += vx * vx;
                            cs[j][1] += vy; cq[j][1] += vy * vy;
                        }
                    }
                }
            }
        }
        if (stats) {
#pragma unroll
            for (int j = 0; j < 4; j++)
#pragma unroll
                for (int h = 0; h < 2; h++) {
#pragma unroll
                    for (int off = 16; off >= 4; off >>= 1) {
                        cs[j][h] += __shfl_down_sync(0xffffffff, cs[j][h], off);
                        cq[j][h] += __shfl_down_sync(0xffffffff, cq[j][h], off);
                    }
                }
            if (lane < 4) {
#pragma unroll
                for (int j = 0; j < 4; j++)
#pragma unroll
                    for (int h = 0; h < 2; h++) {
                        int col = n0 + warp_n * 32 + j * 8 + 2 * lane + h;
                        if (col < D) {
                            atomicAdd(&g_colsum[col], cs[j][h]);
                            atomicAdd(&g_colsq[col], cq[j][h]);
                        }
                    }
            }
        }
    }
}

// ---------------- input embedding -------------------------------------------
__global__ __launch_bounds__(LDH)
void init_h_kernel(const int* __restrict__ x,
                   const float* __restrict__ t1,
                   const float* __restrict__ t2) {
    int f = threadIdx.x;
    size_t i = blockIdx.x;
    float v = 0.f;
    if (f < D) {
        int a = x[2 * i];
        int b = x[2 * i + 1];
        v = t1[a * D + f] + t2[b * D + f];
    }
    g_h[i * LDH + f] = v;
}

// ---------------- weight / bias packing (fp32 -> fp16 hi/lo, padded) --------
__global__ __launch_bounds__(LDH)
void pack_w1_kernel(const float* __restrict__ w1) {
    int k = threadIdx.x;
    int r = blockIdx.x;
    int l = r / 640, row = r % 640;
    float v = 0.f;
    if (row < 600 && k < D) v = w1[(size_t)(l * 600 + row) * D + k];
    __half hi, lo;
    split_h(v, hi, lo);
    g_w1hi[(size_t)r * LDH + k] = hi;
    g_w1lo[(size_t)r * LDH + k] = lo;
}
__global__ __launch_bounds__(LDHID)
void pack_w2_kernel(const float* __restrict__ w2) {
    int k = threadIdx.x;
    int r = blockIdx.x;
    int l = r / 384, row = r % 384;
    float v = 0.f;
    if (row < D && k < 600) v = w2[(size_t)(l * D + row) * 600 + k];
    __half hi, lo;
    split_h(v, hi, lo);
    g_w2hi[(size_t)r * LDHID + k] = hi;
    g_w2lo[(size_t)r * LDHID + k] = lo;
}
__global__ __launch_bounds__(256)
void pack_b1_kernel(const float* __restrict__ b1) {
    int i = blockIdx.x * 256 + threadIdx.x;
    if (i >= NL * 640) return;
    int l = i / 640, c = i % 640;
    g_b1p[i] = (c < 600) ? b1[l * 600 + c] : 0.f;
}
__global__ __launch_bounds__(256)
void pack_b2_kernel(const float* __restrict__ b2) {
    int i = blockIdx.x * 256 + threadIdx.x;
    if (i >= NL * LDH) return;
    int l = i / LDH, c = i % LDH;
    g_b2p[i] = (c < D) ? b2[l * D + c] : 0.f;
}

// ---------------- CSR build (dst-sorted) ------------------------------------
__global__ __launch_bounds__(256)
void zero_cnt_kernel() {
    int i = blockIdx.x * blockDim.x + threadIdx.x;
    if (i < NN) g_cnt[i] = 0;
}
__global__ __launch_bounds__(256)
void hist_kernel(const int* __restrict__ ei) {
    int e = blockIdx.x * blockDim.x + threadIdx.x;
    if (e < NE) atomicAdd(&g_cnt[ei[NE + e]], 1);
}
__global__ __launch_bounds__(512)
void scan_kernel() {
    __shared__ int s[512];
    const int CH = (NN + 511) / 512;
    int t = threadIdx.x;
    int base = t * CH;
    int sum = 0;
#pragma unroll 1
    for (int i = 0; i < CH; i++) {
        int idx = base + i;
        if (idx < NN) sum += g_cnt[idx];
    }
    s[t] = sum;
    __syncthreads();
    for (int off = 1; off < 512; off <<= 1) {
        int v = (t >= off) ? s[t - off] : 0;
        __syncthreads();
        s[t] += v;
        __syncthreads();
    }
    int run = s[t] - sum;
#pragma unroll 1
    for (int i = 0; i < CH; i++) {
        int idx = base + i;
        if (idx < NN) { g_rowptr[idx] = run; run += g_cnt[idx]; }
    }
    if (t == 511) g_rowptr[NN] = s[511];
}
__global__ __launch_bounds__(256)
void scatter_kernel(const int* __restrict__ ei,
                    const int* __restrict__ ea) {
    int e = blockIdx.x * blockDim.x + threadIdx.x;
    if (e >= NE) return;
    int srcv = ei[e];
    int dstv = ei[NE + e];
    int pos = g_rowptr[dstv] + atomicAdd(&g_cnt[dstv], 1);
    g_src[pos] = srcv;
    g_ec[pos] = (unsigned char)(ea[2 * e] * 3 + ea[2 * e + 1]);
}

// ---------------- gather-aggregate with fused BN+ReLU ------------------------
__global__ __launch_bounds__(256)
void agg_kernel(const float* __restrict__ X,
                const float* __restrict__ e1,
                const float* __restrict__ e2,
                int transform) {
    __shared__ float etab[18 * D];
    int tid = threadIdx.x;
    for (int idx = tid; idx < 18 * D; idx += 256) {
        int c = idx / D, f = idx - c * D;
        etab[idx] = e1[(c / 3) * D + f] + e2[(c % 3) * D + f];
    }
    __syncthreads();
    int warp = tid >> 5, lane = tid & 31;
    int node = blockIdx.x * 8 + warp;
    if (node >= NN) return;

    float sc[10], sh[10];
#pragma unroll
    for (int j = 0; j < 10; j++) {
        int f = lane + 32 * j;
        if (transform && f < D) { sc[j] = g_scale[f]; sh[j] = g_shift[f]; }
        else { sc[j] = 1.f; sh[j] = 0.f; }
    }

    float acc[10];
    const float* hr = X + (size_t)node * LDH;
#pragma unroll
    for (int j = 0; j < 10; j++) {
        int f = lane + 32 * j;
        if (f < D) {
            float v = fmaf(hr[f], sc[j], sh[j]);
            if (transform) v = fmaxf(v, 0.f);
            acc[j] = v + etab[12 * D + f];   // self loop code 12
        } else acc[j] = 0.f;
    }
    int beg = g_rowptr[node];
    int end = g_rowptr[node + 1];
#pragma unroll 1
    for (int e = beg; e < end; e++) {
        int s = g_src[e];
        const float* et = etab + (int)g_ec[e] * D;
        const float* hs = X + (size_t)s * LDH;
#pragma unroll
        for (int j = 0; j < 10; j++) {
            int f = lane + 32 * j;
            if (f < D) {
                float v = fmaf(hs[f], sc[j], sh[j]);
                if (transform) v = fmaxf(v, 0.f);
                acc[j] += v + et[f];
            }
        }
    }
    size_t base = (size_t)node * LDH;
#pragma unroll
    for (int j = 0; j < 10; j++) {
        int f = lane + 32 * j;
        float v = (f < D) ? acc[j] : 0.f;
        __half hi, lo;
        split_h(v, hi, lo);
        g_agg_hi[base + f] = hi;
        g_agg_lo[base + f] = lo;
    }
}

// ---------------- BatchNorm helpers -----------------------------------------
__global__ __launch_bounds__(LDH)
void zero_stats_kernel() {
    int f = threadIdx.x;
    g_colsum[f] = 0.f; g_colsq[f] = 0.f;
}
__global__ __launch_bounds__(LDH)
void bn_final_kernel(const float* __restrict__ gamma,
                     const float* __restrict__ beta) {
    int f = threadIdx.x;
    if (f < D) {
        float inv_n = 1.f / (float)NN;
        float mean = g_colsum[f] * inv_n;
        float var  = g_colsq[f] * inv_n - mean * mean;
        float sc = gamma[f] * rsqrtf(var + 1e-5f);
        g_scale[f] = sc;
        g_shift[f] = beta[f] - mean * sc;
    }
    // reset stats for the next layer (saves a launch)
    g_colsum[f] = 0.f;
    g_colsq[f] = 0.f;
}
__global__ __launch_bounds__(LDH)
void bn_apply_out_kernel(const float* __restrict__ X, float* __restrict__ out) {
    int f = threadIdx.x;
    if (f >= D) return;
    size_t i = blockIdx.x;
    out[i * (size_t)D + f] = X[i * LDH + f] * g_scale[f] + g_shift[f];
}

// ---------------- launch ----------------------------------------------------
extern "C" void kernel_launch(void* const* d_in, const int* in_sizes, int n_in,
                              void* d_out, int out_size) {
    const int*   x     = (const int*)d_in[0];
    const int*   ei    = (const int*)d_in[1];
    const int*   ea    = (const int*)d_in[2];
    const float* xe1   = (const float*)d_in[3];
    const float* xe2   = (const float*)d_in[4];
    const float* ee1   = (const float*)d_in[5];
    const float* ee2   = (const float*)d_in[6];
    const float* w1    = (const float*)d_in[7];
    const float* b1    = (const float*)d_in[8];
    const float* w2    = (const float*)d_in[9];
    const float* b2    = (const float*)d_in[10];
    const float* gamma = (const float*)d_in[11];
    const float* beta  = (const float*)d_in[12];
    float* out = (float*)d_out;

    float *h, *h2, *b1p, *b2p;
    __half *agg_hi, *agg_lo, *hid_hi, *hid_lo, *w1hi, *w1lo, *w2hi, *w2lo;
    cudaGetSymbolAddress((void**)&h,      g_h);
    cudaGetSymbolAddress((void**)&h2,     g_h2);
    cudaGetSymbolAddress((void**)&agg_hi, g_agg_hi);
    cudaGetSymbolAddress((void**)&agg_lo, g_agg_lo);
    cudaGetSymbolAddress((void**)&hid_hi, g_hid_hi);
    cudaGetSymbolAddress((void**)&hid_lo, g_hid_lo);
    cudaGetSymbolAddress((void**)&w1hi,   g_w1hi);
    cudaGetSymbolAddress((void**)&w1lo,   g_w1lo);
    cudaGetSymbolAddress((void**)&w2hi,   g_w2hi);
    cudaGetSymbolAddress((void**)&w2lo,   g_w2lo);
    cudaGetSymbolAddress((void**)&b1p,    g_b1p);
    cudaGetSymbolAddress((void**)&b2p,    g_b2p);

    static int smem_set = 0;
    if (!smem_set) {
        cudaFuncSetAttribute(hgemm_kernel,
                             cudaFuncAttributeMaxDynamicSharedMemorySize, GEMM_SMEM);
        smem_set = 1;
    }

    // prep
    pack_w1_kernel<<<NL * 640, LDH>>>(w1);
    pack_w2_kernel<<<NL * 384, LDHID>>>(w2);
    pack_b1_kernel<<<(NL * 640 + 255) / 256, 256>>>(b1);
    pack_b2_kernel<<<(NL * LDH + 255) / 256, 256>>>(b2);
    zero_stats_kernel<<<1, LDH>>>();
    init_h_kernel<<<NN, LDH>>>(x, xe1, xe2);

    // CSR build
    zero_cnt_kernel<<<(NN + 255) / 256, 256>>>();
    hist_kernel<<<(NE + 255) / 256, 256>>>(ei);
    scan_kernel<<<1, 512>>>();
    zero_cnt_kernel<<<(NN + 255) / 256, 256>>>();
    scatter_kernel<<<(NE + 255) / 256, 256>>>(ei, ea);

    const int MT = (NN + 127) / 128;   // 782
    for (int l = 0; l < NL; l++) {
        agg_kernel<<<(NN + 7) / 8, 256>>>(l == 0 ? h : h2,
                                          ee1 + l * 6 * D, ee2 + l * 3 * D,
                                          l > 0 ? 1 : 0);

        // GEMM1: N 608 (warp-granular tail), K 19 k16-steps (=304, true 300)
        hgemm_kernel<<<dim3(5, MT), 256, GEMM_SMEM>>>(
            agg_hi, agg_lo, LDH,
            w1hi + (size_t)l * 640 * LDH, w1lo + (size_t)l * 640 * LDH, LDH,
            nullptr, hid_hi, hid_lo, LDHID, b1p + l * 640,
            NN, 608, 19, 1, 0);

        // GEMM2: N 320 (warp-granular tail), K 38 k16-steps (=608), stats fused
        hgemm_kernel<<<dim3(3, MT), 256, GEMM_SMEM>>>(
            hid_hi, hid_lo, LDHID,
            w2hi + (size_t)l * 384 * LDHID, w2lo + (size_t)l * 384 * LDHID, LDHID,
            h2, nullptr, nullptr, LDH, b2p + l * LDH,
            NN, 320, 38, 0, 1);

        bn_final_kernel<<<1, LDH>>>(gamma + l * D, beta + l * D);

        if (l == NL - 1)
            bn_apply_out_kernel<<<NN, LDH>>>(h2, out);
    }
}

// round 14
// speedup vs baseline: 2.4647x; 1.0970x over previous
#include <cuda_runtime.h>
#include <cuda_fp16.h>
#include <cstdint>

#define NN 100000
#define NE 250000
#define D  300
#define LDH 320
#define LDHID 640
#define NL 5

// ---------------- device-global scratch ------------------------------------
__device__ float  g_h  [(size_t)NN * LDH];
__device__ __half g_agg_hi[(size_t)NN * LDH];
__device__ __half g_agg_lo[(size_t)NN * LDH];
__device__ __half g_hid_hi[(size_t)NN * LDHID];
__device__ __half g_hid_lo[(size_t)NN * LDHID];
__device__ float  g_h2 [(size_t)NN * LDH];
__device__ __half g_w1hi[NL * 640 * LDH];
__device__ __half g_w1lo[NL * 640 * LDH];
__device__ __half g_w2hi[NL * 384 * LDHID];
__device__ __half g_w2lo[NL * 384 * LDHID];
__device__ float  g_b1p[NL * 640];
__device__ float  g_b2p[NL * LDH];
__device__ int    g_rowptr[NN + 1];
__device__ int    g_cnt[NN];
__device__ int    g_src[NE];
__device__ unsigned char g_ec[NE];
__device__ float  g_colsum[LDH], g_colsq[LDH], g_scale[LDH], g_shift[LDH];

// ---------------- PTX helpers ----------------------------------------------
__device__ __forceinline__ uint32_t smem_u32(const void* p) {
    uint32_t a;
    asm("{ .reg .u64 t; cvta.to.shared.u64 t, %1; cvt.u32.u64 %0, t; }"
        : "=r"(a) : "l"(p));
    return a;
}
__device__ __forceinline__ void cp16(uint32_t dst, const void* src, int srcbytes) {
    asm volatile("cp.async.cg.shared.global [%0], [%1], 16, %2;"
                 :: "r"(dst), "l"(src), "r"(srcbytes) : "memory");
}
#define CP_COMMIT() asm volatile("cp.async.commit_group;" ::: "memory")
#define CP_WAIT1()  asm volatile("cp.async.wait_group 1;" ::: "memory")
#define CP_WAIT0()  asm volatile("cp.async.wait_group 0;" ::: "memory")

__device__ __forceinline__ void mma_h(float* c, const uint32_t* a,
                                      uint32_t b0, uint32_t b1) {
    asm volatile(
        "mma.sync.aligned.m16n8k16.row.col.f32.f16.f16.f32 "
        "{%0,%1,%2,%3}, {%4,%5,%6,%7}, {%8,%9}, {%0,%1,%2,%3};"
        : "+f"(c[0]), "+f"(c[1]), "+f"(c[2]), "+f"(c[3])
        : "r"(a[0]), "r"(a[1]), "r"(a[2]), "r"(a[3]), "r"(b0), "r"(b1));
}
__device__ __forceinline__ void ldsm4(uint32_t& r0, uint32_t& r1,
                                      uint32_t& r2, uint32_t& r3, uint32_t addr) {
    asm volatile("ldmatrix.sync.aligned.m8n8.x4.shared.b16 {%0,%1,%2,%3}, [%4];"
                 : "=r"(r0), "=r"(r1), "=r"(r2), "=r"(r3) : "r"(addr));
}

__device__ __forceinline__ void split_h(float v, __half& hi, __half& lo) {
    hi = __float2half(v);
    lo = __float2half(v - __half2float(hi));
}

// ---------------- 3-term fp16 split GEMM: C = A(MxK)*B(NxK)^T + bias --------
// All MMAs fp16 f32-accumulate: ah*bh + ah*bl + al*bh.
// CTA tile 128x128 (N tail warp-granular), K in k16 steps (odd tail skipped
// via one warp-uniform branch), 3-stage cp.async pipeline with ONE
// __syncthreads per chunk, XOR-swizzled 64B-stride smem (conflict-free
// ldmatrix + stores), 8 warps (2Mx4N), warp tile 64x32, occupancy 2.
#define SROW 64                          // smem row stride bytes (no pad)
#define TILE_B 8192                      // 128 rows x 64 B
#define STAGE_B (4 * TILE_B)             // Ah, Al, Bh, Bl = 32768
#define GEMM_SMEM (3 * STAGE_B)          // 98304

__global__ __launch_bounds__(256, 2)
void hgemm_kernel(const __half* __restrict__ Ahi, const __half* __restrict__ Alo, int lda,
                  const __half* __restrict__ Bhi, const __half* __restrict__ Blo, int ldb,
                  float* __restrict__ Cf, __half* __restrict__ Chi, __half* __restrict__ Clo,
                  int ldc, const float* __restrict__ bias,
                  int M, int Npad, int nks, int outmode, int stats) {
    extern __shared__ uint32_t smu[];
    uint32_t sbase = smem_u32(smu);
    int tid = threadIdx.x;
    int wid = tid >> 5, lane = tid & 31;
    int warp_m = wid & 1, warp_n = wid >> 1;     // 2 x 4
    int g = lane >> 2, t = lane & 3;

    int m0 = blockIdx.y * 128;
    int n0 = blockIdx.x * 128;
    bool active = (warp_n * 32) < (Npad - n0);   // warp-granular N tail
    int nch = (nks + 1) >> 1;                    // number of 32-wide chunks

    float acc[4][4][4];
#pragma unroll
    for (int i = 0; i < 4; i++)
#pragma unroll
        for (int j = 0; j < 4; j++)
#pragma unroll
            for (int r = 0; r < 4; r++) acc[i][j][r] = 0.f;

    // ldmatrix lane bases; swizzle select is lane-constant (row+16i keeps it)
    int la_row = warp_m * 64 + (lane & 15);
    int a_b = lane >> 4;                 // k-half segment bit
    int a_sw = (la_row >> 1) & 3;
    int lb_row = warp_n * 32 + (lane & 7) + ((lane >> 4) * 8);
    int b_b = (lane >> 3) & 1;
    int b_sw = (lb_row >> 1) & 3;

#define LOAD_CHUNK(slot, kc) do {                                             \
    uint32_t st = sbase + (slot) * STAGE_B;                                   \
    _Pragma("unroll")                                                         \
    for (int it = 0; it < 2; it++) {                                          \
        int u = it * 256 + tid;                                               \
        int row = u >> 2, seg = u & 3;                                        \
        uint32_t so = (uint32_t)(row * SROW + ((seg ^ ((row >> 1) & 3)) * 16)); \
        int gr = m0 + row;                                                    \
        bool va = gr < M;                                                     \
        size_t aoff = (size_t)(va ? gr : 0) * lda + (kc) * 32 + seg * 8;      \
        cp16(st + so, Ahi + aoff, va ? 16 : 0);                               \
        cp16(st + TILE_B + so, Alo + aoff, va ? 16 : 0);                      \
        size_t boff = (size_t)(n0 + row) * ldb + (kc) * 32 + seg * 8;         \
        cp16(st + 2 * TILE_B + so, Bhi + boff, 16);                           \
        cp16(st + 3 * TILE_B + so, Blo + boff, 16);                           \
    }                                                                         \
} while (0)

// straight-line body for one k16 step (no internal branches)
#define DO_KS(ks) do {                                                        \
    uint32_t aseg = (uint32_t)((((ks) * 2 + a_b) ^ a_sw) * 16);               \
    uint32_t bseg = (uint32_t)((((ks) * 2 + b_b) ^ b_sw) * 16);               \
    uint32_t ah[4][4], al[4][4];                                              \
    _Pragma("unroll")                                                         \
    for (int i = 0; i < 4; i++) {                                             \
        uint32_t off = (uint32_t)((la_row + i * 16) * SROW) + aseg;           \
        ldsm4(ah[i][0], ah[i][1], ah[i][2], ah[i][3], tAh + off);             \
        ldsm4(al[i][0], al[i][1], al[i][2], al[i][3], tAl + off);             \
    }                                                                         \
    uint32_t bh[4][2], bl[4][2];                                              \
    _Pragma("unroll")                                                         \
    for (int jj = 0; jj < 2; jj++) {                                          \
        uint32_t off = (uint32_t)((lb_row + jj * 16) * SROW) + bseg;          \
        ldsm4(bh[2 * jj][0], bh[2 * jj][1], bh[2 * jj + 1][0], bh[2 * jj + 1][1], tBh + off); \
        ldsm4(bl[2 * jj][0], bl[2 * jj][1], bl[2 * jj + 1][0], bl[2 * jj + 1][1], tBl + off); \
    }                                                                         \
    _Pragma("unroll")                                                         \
    for (int j = 0; j < 4; j++) {                                             \
        _Pragma("unroll")                                                     \
        for (int i = 0; i < 4; i++) {                                         \
            mma_h(acc[i][j], ah[i], bh[j][0], bh[j][1]);                      \
            mma_h(acc[i][j], ah[i], bl[j][0], bl[j][1]);                      \
            mma_h(acc[i][j], al[i], bh[j][0], bh[j][1]);                      \
        }                                                                     \
    }                                                                         \
} while (0)

    LOAD_CHUNK(0, 0);
    CP_COMMIT();
    if (nch > 1) LOAD_CHUNK(1, 1);
    CP_COMMIT();

    int cs = 0;                 // compute slot
    int ls = 2;                 // load slot (= (cs+2)%3)
    for (int k = 0; k < nch; k++) {
        if (k + 1 < nch) { CP_WAIT1(); } else { CP_WAIT0(); }
        __syncthreads();        // single barrier per chunk (3-stage invariant)
        if (k + 2 < nch) {
            LOAD_CHUNK(ls, k + 2);
            CP_COMMIT();
        }
        uint32_t st = sbase + cs * STAGE_B;
        uint32_t tAh = st, tAl = st + TILE_B;
        uint32_t tBh = st + 2 * TILE_B, tBl = st + 3 * TILE_B;
        if (active) {
            DO_KS(0);
            if (2 * k + 2 <= nks) {      // warp-uniform: skip only the odd tail
                DO_KS(1);
            }
        }
        cs = (cs == 2) ? 0 : cs + 1;
        ls = (ls == 2) ? 0 : ls + 1;
    }
#undef DO_KS
#undef LOAD_CHUNK

    // epilogue
    if (active) {
        float csum[4][2], csq[4][2];
#pragma unroll
        for (int j = 0; j < 4; j++) {
            csum[j][0] = csum[j][1] = 0.f;
            csq[j][0] = csq[j][1] = 0.f;
        }
#pragma unroll
        for (int i = 0; i < 4; i++) {
            int row = m0 + warp_m * 64 + i * 16 + g;
#pragma unroll
            for (int j = 0; j < 4; j++) {
                int col = n0 + warp_n * 32 + j * 8 + 2 * t;
                if (col >= Npad) continue;
                float2 bv = *(const float2*)(bias + col);
#pragma unroll
                for (int h = 0; h < 2; h++) {
                    int r = row + h * 8;
                    if (r >= M) continue;
                    float vx = acc[i][j][2 * h + 0] + bv.x;
                    float vy = acc[i][j][2 * h + 1] + bv.y;
                    if (outmode == 1) {
                        vx = fmaxf(vx, 0.f); vy = fmaxf(vy, 0.f);
                        __half hx, lx, hy, ly;
                        split_h(vx, hx, lx);
                        split_h(vy, hy, ly);
                        *(half2*)(Chi + (size_t)r * ldc + col) = __halves2half2(hx, hy);
                        *(half2*)(Clo + (size_t)r * ldc + col) = __halves2half2(lx, ly);
                    } else {
                        float2 v; v.x = vx; v.y = vy;
                        *(float2*)(Cf + (size_t)r * ldc + col) = v;
                        if (stats) {
                            csum[j][0] += vx; csq[j][0] += vx * vx;
                            csum[j][1] += vy; csq[j][1] += vy * vy;
                        }
                    }
                }
            }
        }
        if (stats) {
#pragma unroll
            for (int j = 0; j < 4; j++)
#pragma unroll
                for (int h = 0; h < 2; h++) {
#pragma unroll
                    for (int off = 16; off >= 4; off >>= 1) {
                        csum[j][h] += __shfl_down_sync(0xffffffff, csum[j][h], off);
                        csq[j][h]  += __shfl_down_sync(0xffffffff, csq[j][h], off);
                    }
                }
            if (lane < 4) {
#pragma unroll
                for (int j = 0; j < 4; j++)
#pragma unroll
                    for (int h = 0; h < 2; h++) {
                        int col = n0 + warp_n * 32 + j * 8 + 2 * lane + h;
                        if (col < D) {
                            atomicAdd(&g_colsum[col], csum[j][h]);
                            atomicAdd(&g_colsq[col], csq[j][h]);
                        }
                    }
            }
        }
    }
}

// ---------------- input embedding -------------------------------------------
__global__ __launch_bounds__(LDH)
void init_h_kernel(const int* __restrict__ x,
                   const float* __restrict__ t1,
                   const float* __restrict__ t2) {
    int f = threadIdx.x;
    size_t i = blockIdx.x;
    float v = 0.f;
    if (f < D) {
        int a = x[2 * i];
        int b = x[2 * i + 1];
        v = t1[a * D + f] + t2[b * D + f];
    }
    g_h[i * LDH + f] = v;
}

// ---------------- weight / bias packing (fp32 -> fp16 hi/lo, padded) --------
__global__ __launch_bounds__(LDH)
void pack_w1_kernel(const float* __restrict__ w1) {
    int k = threadIdx.x;
    int r = blockIdx.x;
    int l = r / 640, row = r % 640;
    float v = 0.f;
    if (row < 600 && k < D) v = w1[(size_t)(l * 600 + row) * D + k];
    __half hi, lo;
    split_h(v, hi, lo);
    g_w1hi[(size_t)r * LDH + k] = hi;
    g_w1lo[(size_t)r * LDH + k] = lo;
}
__global__ __launch_bounds__(LDHID)
void pack_w2_kernel(const float* __restrict__ w2) {
    int k = threadIdx.x;
    int r = blockIdx.x;
    int l = r / 384, row = r % 384;
    float v = 0.f;
    if (row < D && k < 600) v = w2[(size_t)(l * D + row) * 600 + k];
    __half hi, lo;
    split_h(v, hi, lo);
    g_w2hi[(size_t)r * LDHID + k] = hi;
    g_w2lo[(size_t)r * LDHID + k] = lo;
}
__global__ __launch_bounds__(256)
void pack_b1_kernel(const float* __restrict__ b1) {
    int i = blockIdx.x * 256 + threadIdx.x;
    if (i >= NL * 640) return;
    int l = i / 640, c = i % 640;
    g_b1p[i] = (c < 600) ? b1[l * 600 + c] : 0.f;
}
__global__ __launch_bounds__(256)
void pack_b2_kernel(const float* __restrict__ b2) {
    int i = blockIdx.x * 256 + threadIdx.x;
    if (i >= NL * LDH) return;
    int l = i / LDH, c = i % LDH;
    g_b2p[i] = (c < D) ? b2[l * D + c] : 0.f;
}

// ---------------- CSR build (dst-sorted) ------------------------------------
__global__ __launch_bounds__(256)
void zero_cnt_kernel() {
    int i = blockIdx.x * blockDim.x + threadIdx.x;
    if (i < NN) g_cnt[i] = 0;
}
__global__ __launch_bounds__(256)
void hist_kernel(const int* __restrict__ ei) {
    int e = blockIdx.x * blockDim.x + threadIdx.x;
    if (e < NE) atomicAdd(&g_cnt[ei[NE + e]], 1);
}
__global__ __launch_bounds__(512)
void scan_kernel() {
    __shared__ int s[512];
    const int CH = (NN + 511) / 512;
    int t = threadIdx.x;
    int base = t * CH;
    int sum = 0;
#pragma unroll 1
    for (int i = 0; i < CH; i++) {
        int idx = base + i;
        if (idx < NN) sum += g_cnt[idx];
    }
    s[t] = sum;
    __syncthreads();
    for (int off = 1; off < 512; off <<= 1) {
        int v = (t >= off) ? s[t - off] : 0;
        __syncthreads();
        s[t] += v;
        __syncthreads();
    }
    int run = s[t] - sum;
#pragma unroll 1
    for (int i = 0; i < CH; i++) {
        int idx = base + i;
        if (idx < NN) { g_rowptr[idx] = run; run += g_cnt[idx]; }
    }
    if (t == 511) g_rowptr[NN] = s[511];
}
__global__ __launch_bounds__(256)
void scatter_kernel(const int* __restrict__ ei,
                    const int* __restrict__ ea) {
    int e = blockIdx.x * blockDim.x + threadIdx.x;
    if (e >= NE) return;
    int srcv = ei[e];
    int dstv = ei[NE + e];
    int pos = g_rowptr[dstv] + atomicAdd(&g_cnt[dstv], 1);
    g_src[pos] = srcv;
    g_ec[pos] = (unsigned char)(ea[2 * e] * 3 + ea[2 * e + 1]);
}

// ---------------- gather-aggregate with fused BN+ReLU ------------------------
__global__ __launch_bounds__(256)
void agg_kernel(const float* __restrict__ X,
                const float* __restrict__ e1,
                const float* __restrict__ e2,
                int transform) {
    __shared__ float etab[18 * D];
    int tid = threadIdx.x;
    for (int idx = tid; idx < 18 * D; idx += 256) {
        int c = idx / D, f = idx - c * D;
        etab[idx] = e1[(c / 3) * D + f] + e2[(c % 3) * D + f];
    }
    __syncthreads();
    int warp = tid >> 5, lane = tid & 31;
    int node = blockIdx.x * 8 + warp;
    if (node >= NN) return;

    float sc[10], sh[10];
#pragma unroll
    for (int j = 0; j < 10; j++) {
        int f = lane + 32 * j;
        if (transform && f < D) { sc[j] = g_scale[f]; sh[j] = g_shift[f]; }
        else { sc[j] = 1.f; sh[j] = 0.f; }
    }

    float acc[10];
    const float* hr = X + (size_t)node * LDH;
#pragma unroll
    for (int j = 0; j < 10; j++) {
        int f = lane + 32 * j;
        if (f < D) {
            float v = fmaf(hr[f], sc[j], sh[j]);
            if (transform) v = fmaxf(v, 0.f);
            acc[j] = v + etab[12 * D + f];   // self loop code 12
        } else acc[j] = 0.f;
    }
    int beg = g_rowptr[node];
    int end = g_rowptr[node + 1];
#pragma unroll 1
    for (int e = beg; e < end; e++) {
        int s = g_src[e];
        const float* et = etab + (int)g_ec[e] * D;
        const float* hs = X + (size_t)s * LDH;
#pragma unroll
        for (int j = 0; j < 10; j++) {
            int f = lane + 32 * j;
            if (f < D) {
                float v = fmaf(hs[f], sc[j], sh[j]);
                if (transform) v = fmaxf(v, 0.f);
                acc[j] += v + et[f];
            }
        }
    }
    size_t base = (size_t)node * LDH;
#pragma unroll
    for (int j = 0; j < 10; j++) {
        int f = lane + 32 * j;
        float v = (f < D) ? acc[j] : 0.f;
        __half hi, lo;
        split_h(v, hi, lo);
        g_agg_hi[base + f] = hi;
        g_agg_lo[base + f] = lo;
    }
}

// ---------------- BatchNorm helpers -----------------------------------------
__global__ __launch_bounds__(LDH)
void zero_stats_kernel() {
    int f = threadIdx.x;
    g_colsum[f] = 0.f; g_colsq[f] = 0.f;
}
__global__ __launch_bounds__(LDH)
void bn_final_kernel(const float* __restrict__ gamma,
                     const float* __restrict__ beta) {
    int f = threadIdx.x;
    if (f < D) {
        float inv_n = 1.f / (float)NN;
        float mean = g_colsum[f] * inv_n;
        float var  = g_colsq[f] * inv_n - mean * mean;
        float sc = gamma[f] * rsqrtf(var + 1e-5f);
        g_scale[f] = sc;
        g_shift[f] = beta[f] - mean * sc;
    }
    // reset stats for the next layer (saves a launch)
    g_colsum[f] = 0.f;
    g_colsq[f] = 0.f;
}
__global__ __launch_bounds__(LDH)
void bn_apply_out_kernel(const float* __restrict__ X, float* __restrict__ out) {
    int f = threadIdx.x;
    if (f >= D) return;
    size_t i = blockIdx.x;
    out[i * (size_t)D + f] = X[i * LDH + f] * g_scale[f] + g_shift[f];
}

// ---------------- launch ----------------------------------------------------
extern "C" void kernel_launch(void* const* d_in, const int* in_sizes, int n_in,
                              void* d_out, int out_size) {
    const int*   x     = (const int*)d_in[0];
    const int*   ei    = (const int*)d_in[1];
    const int*   ea    = (const int*)d_in[2];
    const float* xe1   = (const float*)d_in[3];
    const float* xe2   = (const float*)d_in[4];
    const float* ee1   = (const float*)d_in[5];
    const float* ee2   = (const float*)d_in[6];
    const float* w1    = (const float*)d_in[7];
    const float* b1    = (const float*)d_in[8];
    const float* w2    = (const float*)d_in[9];
    const float* b2    = (const float*)d_in[10];
    const float* gamma = (const float*)d_in[11];
    const float* beta  = (const float*)d_in[12];
    float* out = (float*)d_out;

    float *h, *h2, *b1p, *b2p;
    __half *agg_hi, *agg_lo, *hid_hi, *hid_lo, *w1hi, *w1lo, *w2hi, *w2lo;
    cudaGetSymbolAddress((void**)&h,      g_h);
    cudaGetSymbolAddress((void**)&h2,     g_h2);
    cudaGetSymbolAddress((void**)&agg_hi, g_agg_hi);
    cudaGetSymbolAddress((void**)&agg_lo, g_agg_lo);
    cudaGetSymbolAddress((void**)&hid_hi, g_hid_hi);
    cudaGetSymbolAddress((void**)&hid_lo, g_hid_lo);
    cudaGetSymbolAddress((void**)&w1hi,   g_w1hi);
    cudaGetSymbolAddress((void**)&w1lo,   g_w1lo);
    cudaGetSymbolAddress((void**)&w2hi,   g_w2hi);
    cudaGetSymbolAddress((void**)&w2lo,   g_w2lo);
    cudaGetSymbolAddress((void**)&b1p,    g_b1p);
    cudaGetSymbolAddress((void**)&b2p,    g_b2p);

    static int smem_set = 0;
    if (!smem_set) {
        cudaFuncSetAttribute(hgemm_kernel,
                             cudaFuncAttributeMaxDynamicSharedMemorySize, GEMM_SMEM);
        smem_set = 1;
    }

    // prep
    pack_w1_kernel<<<NL * 640, LDH>>>(w1);
    pack_w2_kernel<<<NL * 384, LDHID>>>(w2);
    pack_b1_kernel<<<(NL * 640 + 255) / 256, 256>>>(b1);
    pack_b2_kernel<<<(NL * LDH + 255) / 256, 256>>>(b2);
    zero_stats_kernel<<<1, LDH>>>();
    init_h_kernel<<<NN, LDH>>>(x, xe1, xe2);

    // CSR build
    zero_cnt_kernel<<<(NN + 255) / 256, 256>>>();
    hist_kernel<<<(NE + 255) / 256, 256>>>(ei);
    scan_kernel<<<1, 512>>>();
    zero_cnt_kernel<<<(NN + 255) / 256, 256>>>();
    scatter_kernel<<<(NE + 255) / 256, 256>>>(ei, ea);

    const int MT = (NN + 127) / 128;   // 782
    for (int l = 0; l < NL; l++) {
        agg_kernel<<<(NN + 7) / 8, 256>>>(l == 0 ? h : h2,
                                          ee1 + l * 6 * D, ee2 + l * 3 * D,
                                          l > 0 ? 1 : 0);

        // GEMM1: N 608 (warp-granular tail), K 19 k16-steps (=304, true 300)
        hgemm_kernel<<<dim3(5, MT), 256, GEMM_SMEM>>>(
            agg_hi, agg_lo, LDH,
            w1hi + (size_t)l * 640 * LDH, w1lo + (size_t)l * 640 * LDH, LDH,
            nullptr, hid_hi, hid_lo, LDHID, b1p + l * 640,
            NN, 608, 19, 1, 0);

        // GEMM2: N 320 (warp-granular tail), K 38 k16-steps (=608), stats fused
        hgemm_kernel<<<dim3(3, MT), 256, GEMM_SMEM>>>(
            hid_hi, hid_lo, LDHID,
            w2hi + (size_t)l * 384 * LDHID, w2lo + (size_t)l * 384 * LDHID, LDHID,
            h2, nullptr, nullptr, LDH, b2p + l * LDH,
            NN, 320, 38, 0, 1);

        bn_final_kernel<<<1, LDH>>>(gamma + l * D, beta + l * D);

        if (l == NL - 1)
            bn_apply_out_kernel<<<NN, LDH>>>(h2, out);
    }
}